// round 13
// baseline (speedup 1.0000x reference)
#include <cuda_runtime.h>
#include <math.h>

#define FULLMASK 0xffffffffu
#define TWO_PI_F 6.2831853071795864f

// ---------------- scratch ----------------
__device__ float g_ts[256 * 256];   // ts angles, row b: [s*64 + g]

// ---------------- sim14 single-layer op schedule (32 ops) ----------------
__constant__ int c_OPC[32] = {
    -1,-1,-1,-1,-1,-1,-1,-1,
     7, 6, 5, 4, 3, 2, 1, 0,
    -1,-1,-1,-1,-1,-1,-1,-1,
     7, 0, 1, 2, 3, 4, 5, 6};
__constant__ int c_OPT[32] = {
     0, 1, 2, 3, 4, 5, 6, 7,
     0, 7, 6, 5, 4, 3, 2, 1,
     0, 1, 2, 3, 4, 5, 6, 7,
     6, 7, 0, 1, 2, 3, 4, 5};

// ---------------- helpers ----------------
__device__ __forceinline__ float g4(float4 v, int i) {
    return (i == 0) ? v.x : (i == 1) ? v.y : (i == 2) ? v.z : v.w;
}
__device__ __forceinline__ float4 splat4(float v) { return make_float4(v, v, v, v); }
__device__ __forceinline__ float silu_f(float x) { return x * (1.f / (1.f + expf(-x))); }
__device__ __forceinline__ float dot4(float4 a, float4 b) {
    float r = a.x * b.x;
    r = fmaf(a.y, b.y, r);
    r = fmaf(a.z, b.z, r);
    r = fmaf(a.w, b.w, r);
    return r;
}
__device__ __forceinline__ float wredsum(float v) {
#pragma unroll
    for (int off = 16; off; off >>= 1) v += __shfl_xor_sync(FULLMASK, v, off);
    return v;
}

// State layout (4 warps per batch element, 128 threads):
//   flat index n (10 bits): bit9..bit5 = wires 0..4 (lane bits 4..0),
//   bit4 = wire5 (tid bit 6), bit3 = wire6 (tid bit 5),
//   bit2 = wire7 (reg M=4), bit1 = wire8/anc0 (M=2), bit0 = wire9/anc1 (M=1).
//   Each thread holds 8 float2 (r = bits 2..0). select index s = r & 3.
#define OIDX(n) ((n) ^ (((n) >> 5) & 31))

// RY on a lane-bit wire
__device__ __forceinline__ void ry_lane(float2 (&st)[8], int lmask, int lb, int lane,
                                        float4 c, float4 s) {
    float sg = ((lane >> lb) & 1) ? 1.f : -1.f;
    float4 sv = make_float4(g4(s,0)*sg, g4(s,1)*sg, g4(s,2)*sg, g4(s,3)*sg);
#pragma unroll
    for (int r = 0; r < 8; ++r) {
        float ox = __shfl_xor_sync(FULLMASK, st[r].x, lmask);
        float oy = __shfl_xor_sync(FULLMASK, st[r].y, lmask);
        float pc = g4(c, r & 3), ps = g4(sv, r & 3);
        st[r].x = fmaf(pc, st[r].x, ps * ox);
        st[r].y = fmaf(pc, st[r].y, ps * oy);
    }
}

// RY on a reg-bit wire (mask M in {4,2,1})
template <int M>
__device__ __forceinline__ void ry_reg(float2 (&st)[8], float4 c, float4 s) {
#pragma unroll
    for (int r = 0; r < 8; ++r) {
        if ((r & M) == 0) {
            const int r1 = r | M;
            float pc = g4(c, r & 3), ps = g4(s, r & 3);
            float ax = st[r].x, ay = st[r].y, bx = st[r1].x, by = st[r1].y;
            st[r].x = fmaf(pc, ax, -ps * bx);
            st[r].y = fmaf(pc, ay, -ps * by);
            st[r1].x = fmaf(ps, ax, pc * bx);
            st[r1].y = fmaf(ps, ay, pc * by);
        }
    }
}

// CRX with target on a lane-bit wire. act = actBase && (crm==0 || (r&crm))
__device__ __forceinline__ void crx_lane(float2 (&st)[8], int tmask,
                                         bool actBase, int crm,
                                         float4 c, float4 s) {
#pragma unroll
    for (int r = 0; r < 8; ++r) {
        float ox = __shfl_xor_sync(FULLMASK, st[r].x, tmask);
        float oy = __shfl_xor_sync(FULLMASK, st[r].y, tmask);
        bool act = actBase && (crm == 0 || (r & crm) != 0);
        float pc = g4(c, r & 3), ps = g4(s, r & 3);
        float nx = fmaf(pc, st[r].x, ps * oy);
        float ny = fmaf(pc, st[r].y, -ps * ox);
        if (act) { st[r].x = nx; st[r].y = ny; }
    }
}

// CRX with target on a reg-bit wire (mask M)
template <int M>
__device__ __forceinline__ void crx_reg(float2 (&st)[8], bool actBase, int crm,
                                        float4 c, float4 s) {
#pragma unroll
    for (int r = 0; r < 8; ++r) {
        if ((r & M) == 0) {
            const int r1 = r | M;
            bool act = actBase && (crm == 0 || (r & crm) != 0);
            float pc = g4(c, r & 3), ps = g4(s, r & 3);
            float ax = st[r].x, ay = st[r].y, bx = st[r1].x, by = st[r1].y;
            float n0x = fmaf(pc, ax, ps * by);
            float n0y = fmaf(pc, ay, -ps * bx);
            float n1x = fmaf(pc, bx, ps * ay);
            float n1y = fmaf(pc, by, -ps * ax);
            if (act) { st[r] = make_float2(n0x, n0y); st[r1] = make_float2(n1x, n1y); }
        }
    }
}

// Op (RY or CRX) targeting a warp bit: smem exchange (float2). xm = 64 (w5) or 32 (w6)
__device__ __forceinline__ void warp_op(float2 (&st)[8], float2* sbuf,
                                        int tid, int xm, bool isRY,
                                        bool actBase, int crm, float4 c, float4 s) {
    __syncthreads();
#pragma unroll
    for (int r = 0; r < 8; ++r) sbuf[r * 128 + tid] = st[r];
    __syncthreads();
    const int p = tid ^ xm;
    const float sg = (tid & xm) ? 1.f : -1.f;
#pragma unroll
    for (int r = 0; r < 8; ++r) {
        float2 o = sbuf[r * 128 + p];
        float pc = g4(c, r & 3), ps = g4(s, r & 3);
        if (isRY) {
            float pss = sg * ps;
            st[r].x = fmaf(pc, st[r].x, pss * o.x);
            st[r].y = fmaf(pc, st[r].y, pss * o.y);
        } else {
            bool act = actBase && (crm == 0 || (r & crm) != 0);
            float nx = fmaf(pc, st[r].x, ps * o.y);
            float ny = fmaf(pc, st[r].y, -ps * o.x);
            if (act) { st[r].x = nx; st[r].y = ny; }
        }
    }
}

// RZ on a reg-bit wire (ancilla)
template <int M>
__device__ __forceinline__ void rz_reg(float2 (&st)[8], float c, float s) {
#pragma unroll
    for (int r = 0; r < 8; ++r) {
        float ss = (r & M) ? s : -s;
        float x = st[r].x, y = st[r].y;
        st[r].x = fmaf(c, x, -ss * y);
        st[r].y = fmaf(c, y, ss * x);
    }
}

__device__ __forceinline__ void cnot_st(float2 (&st)[8]) {
#pragma unroll
    for (int r = 0; r < 8; ++r) {
        if ((r & 3) == 2) { float2 tmp = st[r]; st[r] = st[r | 1]; st[r | 1] = tmp; }
    }
}

__device__ __forceinline__ void pcphase_g(float2 (&st)[8], float cphi, float sphi) {
#pragma unroll
    for (int r = 0; r < 8; ++r) {
        float ss = ((r & 3) == 0) ? sphi : -sphi;
        float x = st[r].x, y = st[r].y;
        st[r].x = fmaf(cphi, x, -ss * y);
        st[r].y = fmaf(cphi, y, ss * x);
    }
}

__device__ __forceinline__ void apply_op(float2 (&st)[8], int lane, int tid,
                                         float2* sbuf,
                                         int cw, int tw, float4 c, float4 s) {
    if (cw < 0) {  // RY
        if (tw < 5)       ry_lane(st, 1 << (4 - tw), 4 - tw, lane, c, s);
        else if (tw == 5) warp_op(st, sbuf, tid, 64, true, true, 0, c, s);
        else if (tw == 6) warp_op(st, sbuf, tid, 32, true, true, 0, c, s);
        else              ry_reg<4>(st, c, s);
    } else {       // CRX
        bool actBase; int crm = 0;
        if (cw < 5)       actBase = ((lane >> (4 - cw)) & 1) != 0;
        else if (cw == 5) actBase = ((tid >> 6) & 1) != 0;
        else if (cw == 6) actBase = ((tid >> 5) & 1) != 0;
        else { actBase = true; crm = 4; }
        if (tw < 5)       crx_lane(st, 1 << (4 - tw), actBase, crm, c, s);
        else if (tw == 5) warp_op(st, sbuf, tid, 64, false, actBase, crm, c, s);
        else if (tw == 6) warp_op(st, sbuf, tid, 32, false, actBase, crm, c, s);
        else              crx_reg<4>(st, actBase, crm, c, s);
    }
}

// sim14 with 2 layers (compact loop, runtime dispatch)
__device__ __forceinline__ void run_sim14_2l(float2 (&st)[8], int lane, int tid,
                                             float2* sbuf,
                                             const float4* tabc, const float4* tabs,
                                             bool adj) {
    if (!adj) {
#pragma unroll 1
        for (int step = 0; step < 64; ++step) {
            int o = step & 31;
            float4 c = tabc[step];
            float4 s = tabs[step];
            apply_op(st, lane, tid, sbuf, c_OPC[o], c_OPT[o], c, s);
        }
    } else {
#pragma unroll 1
        for (int step = 63; step >= 0; --step) {
            int o = step & 31;
            float4 c = tabc[step];
            float4 s0 = tabs[step];
            float4 s = make_float4(-s0.x, -s0.y, -s0.z, -s0.w);
            apply_op(st, lane, tid, sbuf, c_OPC[o], c_OPT[o], c, s);
        }
    }
}

__device__ __forceinline__ void do_prepare(float2 (&st)[8], const float2* tabp, bool adj) {
    if (!adj) {
#pragma unroll
        for (int ly = 0; ly < 2; ++ly) {
            float2 a  = tabp[ly*4+0]; ry_reg<2>(st, splat4(a.x),  splat4(a.y));
            float2 z  = tabp[ly*4+1]; rz_reg<2>(st, z.x, z.y);
            float2 a2 = tabp[ly*4+2]; ry_reg<1>(st, splat4(a2.x), splat4(a2.y));
            float2 z2 = tabp[ly*4+3]; rz_reg<1>(st, z2.x, z2.y);
            cnot_st(st);
        }
    } else {
#pragma unroll
        for (int ly = 1; ly >= 0; --ly) {
            cnot_st(st);
            float2 z2 = tabp[ly*4+3]; rz_reg<1>(st, z2.x, -z2.y);
            float2 a2 = tabp[ly*4+2]; ry_reg<1>(st, splat4(a2.x), splat4(-a2.y));
            float2 z  = tabp[ly*4+1]; rz_reg<2>(st, z.x, -z.y);
            float2 a  = tabp[ly*4+0]; ry_reg<2>(st, splat4(a.x),  splat4(-a.y));
        }
    }
}

// ---------------- simulate kernel: 4 warps per batch element ----------------
__global__ void __launch_bounds__(128) k_sim(
    const float* __restrict__ prep_p, const float* __restrict__ sig,
    const float* __restrict__ qff,
    const float* __restrict__ A_obs, const float* __restrict__ B_obs,
    const float* __restrict__ D_obs,
    const float* __restrict__ head_w, const float* __restrict__ head_b,
    float* __restrict__ out) {
    __shared__ float2 sbuf[1024];   // exchange / obs (8r x 128tid)
    __shared__ float4 tabc[64];
    __shared__ float4 tabs[64];
    __shared__ float2 tabq[32];
    __shared__ float2 tabp[8];
    __shared__ float2 tabsig[4];
    __shared__ float part[28];

    const int tid  = threadIdx.x;
    const int lane = tid & 31;
    const int warp = tid >> 5;
    const int b    = blockIdx.x;
    const float* tsr = g_ts + b * 256;

    if (tid < 64) {
        float c0,s0,c1,s1,c2,s2,c3,s3;
        sincosf(tsr[tid]       * 0.5f, &s0, &c0);
        sincosf(tsr[64 + tid]  * 0.5f, &s1, &c1);
        sincosf(tsr[128 + tid] * 0.5f, &s2, &c2);
        sincosf(tsr[192 + tid] * 0.5f, &s3, &c3);
        tabc[tid] = make_float4(c0, c1, c2, c3);
        tabs[tid] = make_float4(s0, s1, s2, s3);
    } else if (tid < 96) {
        int q = tid - 64;
        float sn, cc; sincosf(qff[q] * 0.5f, &sn, &cc);
        tabq[q] = make_float2(cc, sn);
    } else if (tid < 104) {
        int q = tid - 96;
        float sn, cc; sincosf(prep_p[q] * 0.5f, &sn, &cc);
        tabp[q] = make_float2(cc, sn);
    } else if (tid < 108) {
        int q = tid - 104;
        float sn, cc; sincosf(sig[q], &sn, &cc);
        tabsig[q] = make_float2(cc, sn);
    }
    __syncthreads();

    float2 st[8];
#pragma unroll
    for (int r = 0; r < 8; ++r) st[r] = make_float2(0.f, 0.f);
    if (tid == 0) st[0].x = 1.f;

    { float2 p = tabsig[0]; pcphase_g(st, p.x, p.y); }
#pragma unroll 1
    for (int k = 0; k < 3; ++k) {
        do_prepare(st, tabp, false);
        run_sim14_2l(st, lane, tid, sbuf, tabc, tabs, (k & 1) != 0);
        do_prepare(st, tabp, true);
        float2 p = tabsig[k + 1];
        pcphase_g(st, p.x, p.y);
    }
    // final sim14 with qff params, 1 layer (uniform theta)
#pragma unroll 1
    for (int step = 0; step < 32; ++step) {
        float2 tq = tabq[step];
        apply_op(st, lane, tid, sbuf, c_OPC[step], c_OPT[step],
                 splat4(tq.x), splat4(tq.y));
    }

    // dump state to shared (swizzled) for expectation values
    __syncthreads();
#pragma unroll
    for (int r = 0; r < 8; ++r) {
        int n = (lane << 5) | (warp << 3) | r;
        sbuf[OIDX(n)] = st[r];
    }
    __syncthreads();

#pragma unroll 1
    for (int w = 0; w < 7; ++w) {
        const float* Aw = A_obs + w * 6;
        const float* Bw = B_obs + w * 6;
        const float* Dw = D_obs + w * 4;
        float d0 = 2.f * Dw[1], d1 = 2.f * Dw[2], d2 = 2.f * Dw[3];
        float a10 = Aw[0], b10 = Bw[0], a20 = Aw[1], b20 = Bw[1], a21 = Aw[2], b21 = Bw[2];
        float a30 = Aw[3], b30 = Bw[3], a31 = Aw[4], b31 = Bw[4], a32 = Aw[5], b32 = Bw[5];
        int b1 = 8 - w;
        int m1 = 1 << b1, m0 = m1 << 1;
        int lowmask = m1 - 1;
        float acc = 0.f;
#pragma unroll
        for (int it = 0; it < 2; ++it) {
            int gi = tid + it * 128;
            int n = ((gi & ~lowmask) << 2) | (gi & lowmask);
            float2 v0 = sbuf[OIDX(n)];
            float2 v1 = sbuf[OIDX(n + m1)];
            float2 v2 = sbuf[OIDX(n + m0)];
            float2 v3 = sbuf[OIDX(n + m0 + m1)];
            acc += d0 * (v0.x * v0.x + v0.y * v0.y);
            acc += d1 * (v1.x * v1.x + v1.y * v1.y);
            acc += d2 * (v2.x * v2.x + v2.y * v2.y);
#define CROSS(vi, vj, aa, bb) { \
            float pr = vi.x * vj.x + vi.y * vj.y; \
            float pim = vi.x * vj.y - vi.y * vj.x; \
            acc += 2.f * (pr * (aa) - pim * (bb)); }
            CROSS(v1, v0, a10, b10)
            CROSS(v2, v0, a20, b20)
            CROSS(v2, v1, a21, b21)
            CROSS(v3, v0, a30, b30)
            CROSS(v3, v1, a31, b31)
            CROSS(v3, v2, a32, b32)
#undef CROSS
        }
#pragma unroll
        for (int off = 16; off; off >>= 1) acc += __shfl_xor_sync(FULLMASK, acc, off);
        if (lane == 0) part[w * 4 + warp] = acc;
    }
    __syncthreads();

    // head: out[b][j] = sum_w e[w] * head_w[j*7+w] + head_b[j]
    {
        int j = tid;
        float o = head_b[j];
#pragma unroll
        for (int w = 0; w < 7; ++w) {
            float e = part[w*4] + part[w*4+1] + part[w*4+2] + part[w*4+3];
            o = fmaf(e, head_w[j * 7 + w], o);
        }
        out[b * 128 + j] = o;
    }
}

// ---------------- MLP kernel v2: warp-per-output (coalesced weights) ----------------
// 128 blocks x 256 threads (8 warps); 2 batch rows per block.
__global__ void __launch_bounds__(256) k_mlp(
    const float* __restrict__ t, const float* __restrict__ z_t,
    const float* __restrict__ te_w1, const float* __restrict__ te_b1,
    const float* __restrict__ te_w2, const float* __restrict__ te_b2,
    const float* __restrict__ ip_w1, const float* __restrict__ ip_b1,
    const float* __restrict__ ip_w2, const float* __restrict__ ip_b2) {
    __shared__ float emb[2][128];
    __shared__ float hb[2][128];
    __shared__ float cat[2][256];
    __shared__ float g1[2][256];
    const int tid  = threadIdx.x;
    const int lane = tid & 31;
    const int warp = tid >> 5;
    const int r0 = blockIdx.x * 2;

    // stage A: sinusoidal embedding + copy z_t into cat
    {
        int row = tid >> 7, i = tid & 127;
        float tv = t[r0 + row];
        int ii = i & 63;
        float f = expf(-0.14391156831212787f * (float)ii);
        float a = tv * f;
        emb[row][i] = (i < 64) ? cosf(a) : sinf(a);
        cat[row][i] = z_t[(r0 + row) * 128 + i];
    }
    __syncthreads();

    // stage B: hb = silu(te_w1 @ emb + te_b1). warp-per-output, K=128, J=128.
    {
        float4 x0 = *reinterpret_cast<const float4*>(&emb[0][lane * 4]);
        float4 x1 = *reinterpret_cast<const float4*>(&emb[1][lane * 4]);
#pragma unroll 1
        for (int jj = warp; jj < 128; jj += 8) {
            float4 wv = *reinterpret_cast<const float4*>(te_w1 + jj * 128 + lane * 4);
            float p0 = wredsum(dot4(wv, x0));
            float p1 = wredsum(dot4(wv, x1));
            if (lane == 0) {
                float bb = te_b1[jj];
                hb[0][jj] = silu_f(p0 + bb);
                hb[1][jj] = silu_f(p1 + bb);
            }
        }
    }
    __syncthreads();

    // stage C: cat[.][128+jj] = te_w2 @ hb + te_b2
    {
        float4 x0 = *reinterpret_cast<const float4*>(&hb[0][lane * 4]);
        float4 x1 = *reinterpret_cast<const float4*>(&hb[1][lane * 4]);
#pragma unroll 1
        for (int jj = warp; jj < 128; jj += 8) {
            float4 wv = *reinterpret_cast<const float4*>(te_w2 + jj * 128 + lane * 4);
            float p0 = wredsum(dot4(wv, x0));
            float p1 = wredsum(dot4(wv, x1));
            if (lane == 0) {
                float bb = te_b2[jj];
                cat[0][128 + jj] = p0 + bb;
                cat[1][128 + jj] = p1 + bb;
            }
        }
    }
    __syncthreads();

    // stage D: g1 = silu(ip_w1 @ cat + ip_b1). K=256, J=256.
    {
        float4 xa0 = *reinterpret_cast<const float4*>(&cat[0][lane * 4]);
        float4 xb0 = *reinterpret_cast<const float4*>(&cat[0][128 + lane * 4]);
        float4 xa1 = *reinterpret_cast<const float4*>(&cat[1][lane * 4]);
        float4 xb1 = *reinterpret_cast<const float4*>(&cat[1][128 + lane * 4]);
#pragma unroll 1
        for (int jj = warp; jj < 256; jj += 8) {
            float4 wa = *reinterpret_cast<const float4*>(ip_w1 + jj * 256 + lane * 4);
            float4 wb = *reinterpret_cast<const float4*>(ip_w1 + jj * 256 + 128 + lane * 4);
            float p0 = wredsum(dot4(wa, xa0) + dot4(wb, xb0));
            float p1 = wredsum(dot4(wa, xa1) + dot4(wb, xb1));
            if (lane == 0) {
                float bb = ip_b1[jj];
                g1[0][jj] = silu_f(p0 + bb);
                g1[1][jj] = silu_f(p1 + bb);
            }
        }
    }
    __syncthreads();

    // stage E: ts = sigmoid(ip_w2 @ g1 + ip_b2) * 2pi
    {
        float4 xa0 = *reinterpret_cast<const float4*>(&g1[0][lane * 4]);
        float4 xb0 = *reinterpret_cast<const float4*>(&g1[0][128 + lane * 4]);
        float4 xa1 = *reinterpret_cast<const float4*>(&g1[1][lane * 4]);
        float4 xb1 = *reinterpret_cast<const float4*>(&g1[1][128 + lane * 4]);
#pragma unroll 1
        for (int jj = warp; jj < 256; jj += 8) {
            float4 wa = *reinterpret_cast<const float4*>(ip_w2 + jj * 256 + lane * 4);
            float4 wb = *reinterpret_cast<const float4*>(ip_w2 + jj * 256 + 128 + lane * 4);
            float p0 = wredsum(dot4(wa, xa0) + dot4(wb, xb0));
            float p1 = wredsum(dot4(wa, xa1) + dot4(wb, xb1));
            if (lane == 0) {
                float bb = ip_b2[jj];
                g_ts[r0 * 256 + jj]       = TWO_PI_F / (1.f + expf(-(p0 + bb)));
                g_ts[(r0 + 1) * 256 + jj] = TWO_PI_F / (1.f + expf(-(p1 + bb)));
            }
        }
    }
}

// ---------------- launch ----------------
extern "C" void kernel_launch(void* const* d_in, const int* in_sizes, int n_in,
                              void* d_out, int out_size) {
    const float* z_t    = (const float*)d_in[0];
    const float* t      = (const float*)d_in[1];
    const float* te_w1  = (const float*)d_in[2];
    const float* te_b1  = (const float*)d_in[3];
    const float* te_w2  = (const float*)d_in[4];
    const float* te_b2  = (const float*)d_in[5];
    const float* ip_w1  = (const float*)d_in[6];
    const float* ip_b1  = (const float*)d_in[7];
    const float* ip_w2  = (const float*)d_in[8];
    const float* ip_b2  = (const float*)d_in[9];
    const float* prep   = (const float*)d_in[10];
    const float* sig    = (const float*)d_in[11];
    const float* qff    = (const float*)d_in[12];
    const float* A_obs  = (const float*)d_in[13];
    const float* B_obs  = (const float*)d_in[14];
    const float* D_obs  = (const float*)d_in[15];
    const float* head_w = (const float*)d_in[16];
    const float* head_b = (const float*)d_in[17];
    float* out = (float*)d_out;

    k_mlp<<<128, 256>>>(t, z_t, te_w1, te_b1, te_w2, te_b2, ip_w1, ip_b1, ip_w2, ip_b2);
    k_sim<<<256, 128>>>(prep, sig, qff, A_obs, B_obs, D_obs, head_w, head_b, out);
}

// round 14
// speedup vs baseline: 1.2946x; 1.2946x over previous
#include <cuda_runtime.h>
#include <math.h>

#define FULLMASK 0xffffffffu
#define TWO_PI_F 6.2831853071795864f

// ---------------- sim14 single-layer op schedule (32 ops) ----------------
__constant__ int c_OPC[32] = {
    -1,-1,-1,-1,-1,-1,-1,-1,
     7, 6, 5, 4, 3, 2, 1, 0,
    -1,-1,-1,-1,-1,-1,-1,-1,
     7, 0, 1, 2, 3, 4, 5, 6};
__constant__ int c_OPT[32] = {
     0, 1, 2, 3, 4, 5, 6, 7,
     0, 7, 6, 5, 4, 3, 2, 1,
     0, 1, 2, 3, 4, 5, 6, 7,
     6, 7, 0, 1, 2, 3, 4, 5};

// ---------------- helpers ----------------
__device__ __forceinline__ float g4(float4 v, int i) {
    return (i == 0) ? v.x : (i == 1) ? v.y : (i == 2) ? v.z : v.w;
}
__device__ __forceinline__ float4 splat4(float v) { return make_float4(v, v, v, v); }
__device__ __forceinline__ float silu_f(float x) { return x * (1.f / (1.f + expf(-x))); }

// State layout (4 warps per element; two elements per block, htid = tid & 127):
//   flat index n (10 bits): bit9..bit5 = wires 0..4 (lane bits 4..0),
//   bit4 = wire5 (htid bit 6), bit3 = wire6 (htid bit 5),
//   bit2 = wire7 (reg M=4), bit1 = wire8/anc0 (M=2), bit0 = wire9/anc1 (M=1).
//   Each thread holds 8 float2 (r = bits 2..0). select index s = r & 3.
#define OIDX(n) ((n) ^ (((n) >> 5) & 31))

// RY on a lane-bit wire
__device__ __forceinline__ void ry_lane(float2 (&st)[8], int lmask, int lb, int lane,
                                        float4 c, float4 s) {
    float sg = ((lane >> lb) & 1) ? 1.f : -1.f;
    float4 sv = make_float4(g4(s,0)*sg, g4(s,1)*sg, g4(s,2)*sg, g4(s,3)*sg);
#pragma unroll
    for (int r = 0; r < 8; ++r) {
        float ox = __shfl_xor_sync(FULLMASK, st[r].x, lmask);
        float oy = __shfl_xor_sync(FULLMASK, st[r].y, lmask);
        float pc = g4(c, r & 3), ps = g4(sv, r & 3);
        st[r].x = fmaf(pc, st[r].x, ps * ox);
        st[r].y = fmaf(pc, st[r].y, ps * oy);
    }
}

// RY on a reg-bit wire (mask M in {4,2,1})
template <int M>
__device__ __forceinline__ void ry_reg(float2 (&st)[8], float4 c, float4 s) {
#pragma unroll
    for (int r = 0; r < 8; ++r) {
        if ((r & M) == 0) {
            const int r1 = r | M;
            float pc = g4(c, r & 3), ps = g4(s, r & 3);
            float ax = st[r].x, ay = st[r].y, bx = st[r1].x, by = st[r1].y;
            st[r].x = fmaf(pc, ax, -ps * bx);
            st[r].y = fmaf(pc, ay, -ps * by);
            st[r1].x = fmaf(ps, ax, pc * bx);
            st[r1].y = fmaf(ps, ay, pc * by);
        }
    }
}

// CRX with target on a lane-bit wire
__device__ __forceinline__ void crx_lane(float2 (&st)[8], int tmask,
                                         bool actBase, int crm,
                                         float4 c, float4 s) {
#pragma unroll
    for (int r = 0; r < 8; ++r) {
        float ox = __shfl_xor_sync(FULLMASK, st[r].x, tmask);
        float oy = __shfl_xor_sync(FULLMASK, st[r].y, tmask);
        bool act = actBase && (crm == 0 || (r & crm) != 0);
        float pc = g4(c, r & 3), ps = g4(s, r & 3);
        float nx = fmaf(pc, st[r].x, ps * oy);
        float ny = fmaf(pc, st[r].y, -ps * ox);
        if (act) { st[r].x = nx; st[r].y = ny; }
    }
}

// CRX with target on a reg-bit wire (mask M)
template <int M>
__device__ __forceinline__ void crx_reg(float2 (&st)[8], bool actBase, int crm,
                                        float4 c, float4 s) {
#pragma unroll
    for (int r = 0; r < 8; ++r) {
        if ((r & M) == 0) {
            const int r1 = r | M;
            bool act = actBase && (crm == 0 || (r & crm) != 0);
            float pc = g4(c, r & 3), ps = g4(s, r & 3);
            float ax = st[r].x, ay = st[r].y, bx = st[r1].x, by = st[r1].y;
            float n0x = fmaf(pc, ax, ps * by);
            float n0y = fmaf(pc, ay, -ps * bx);
            float n1x = fmaf(pc, bx, ps * ay);
            float n1y = fmaf(pc, by, -ps * ax);
            if (act) { st[r] = make_float2(n0x, n0y); st[r1] = make_float2(n1x, n1y); }
        }
    }
}

// Op targeting a warp bit: per-half smem exchange. xm = 64 (w5) or 32 (w6).
// Both halves execute the same schedule, so block barriers stay aligned.
__device__ __forceinline__ void warp_op(float2 (&st)[8], float2* sbuf,
                                        int htid, int xm, bool isRY,
                                        bool actBase, int crm, float4 c, float4 s) {
    __syncthreads();
#pragma unroll
    for (int r = 0; r < 8; ++r) sbuf[r * 128 + htid] = st[r];
    __syncthreads();
    const int p = htid ^ xm;
    const float sg = (htid & xm) ? 1.f : -1.f;
#pragma unroll
    for (int r = 0; r < 8; ++r) {
        float2 o = sbuf[r * 128 + p];
        float pc = g4(c, r & 3), ps = g4(s, r & 3);
        if (isRY) {
            float pss = sg * ps;
            st[r].x = fmaf(pc, st[r].x, pss * o.x);
            st[r].y = fmaf(pc, st[r].y, pss * o.y);
        } else {
            bool act = actBase && (crm == 0 || (r & crm) != 0);
            float nx = fmaf(pc, st[r].x, ps * o.y);
            float ny = fmaf(pc, st[r].y, -ps * o.x);
            if (act) { st[r].x = nx; st[r].y = ny; }
        }
    }
}

// RZ on a reg-bit wire (ancilla)
template <int M>
__device__ __forceinline__ void rz_reg(float2 (&st)[8], float c, float s) {
#pragma unroll
    for (int r = 0; r < 8; ++r) {
        float ss = (r & M) ? s : -s;
        float x = st[r].x, y = st[r].y;
        st[r].x = fmaf(c, x, -ss * y);
        st[r].y = fmaf(c, y, ss * x);
    }
}

__device__ __forceinline__ void cnot_st(float2 (&st)[8]) {
#pragma unroll
    for (int r = 0; r < 8; ++r) {
        if ((r & 3) == 2) { float2 tmp = st[r]; st[r] = st[r | 1]; st[r | 1] = tmp; }
    }
}

__device__ __forceinline__ void pcphase_g(float2 (&st)[8], float cphi, float sphi) {
#pragma unroll
    for (int r = 0; r < 8; ++r) {
        float ss = ((r & 3) == 0) ? sphi : -sphi;
        float x = st[r].x, y = st[r].y;
        st[r].x = fmaf(cphi, x, -ss * y);
        st[r].y = fmaf(cphi, y, ss * x);
    }
}

__device__ __forceinline__ void apply_op(float2 (&st)[8], int lane, int htid,
                                         float2* sbuf,
                                         int cw, int tw, float4 c, float4 s) {
    if (cw < 0) {  // RY
        if (tw < 5)       ry_lane(st, 1 << (4 - tw), 4 - tw, lane, c, s);
        else if (tw == 5) warp_op(st, sbuf, htid, 64, true, true, 0, c, s);
        else if (tw == 6) warp_op(st, sbuf, htid, 32, true, true, 0, c, s);
        else              ry_reg<4>(st, c, s);
    } else {       // CRX
        bool actBase; int crm = 0;
        if (cw < 5)       actBase = ((lane >> (4 - cw)) & 1) != 0;
        else if (cw == 5) actBase = ((htid >> 6) & 1) != 0;
        else if (cw == 6) actBase = ((htid >> 5) & 1) != 0;
        else { actBase = true; crm = 4; }
        if (tw < 5)       crx_lane(st, 1 << (4 - tw), actBase, crm, c, s);
        else if (tw == 5) warp_op(st, sbuf, htid, 64, false, actBase, crm, c, s);
        else if (tw == 6) warp_op(st, sbuf, htid, 32, false, actBase, crm, c, s);
        else              crx_reg<4>(st, actBase, crm, c, s);
    }
}

// sim14 with 2 layers (compact loop, runtime dispatch)
__device__ __forceinline__ void run_sim14_2l(float2 (&st)[8], int lane, int htid,
                                             float2* sbuf,
                                             const float4* tabc, const float4* tabs,
                                             bool adj) {
    if (!adj) {
#pragma unroll 1
        for (int step = 0; step < 64; ++step) {
            int o = step & 31;
            float4 c = tabc[step];
            float4 s = tabs[step];
            apply_op(st, lane, htid, sbuf, c_OPC[o], c_OPT[o], c, s);
        }
    } else {
#pragma unroll 1
        for (int step = 63; step >= 0; --step) {
            int o = step & 31;
            float4 c = tabc[step];
            float4 s0 = tabs[step];
            float4 s = make_float4(-s0.x, -s0.y, -s0.z, -s0.w);
            apply_op(st, lane, htid, sbuf, c_OPC[o], c_OPT[o], c, s);
        }
    }
}

__device__ __forceinline__ void do_prepare(float2 (&st)[8], const float2* tabp, bool adj) {
    if (!adj) {
#pragma unroll
        for (int ly = 0; ly < 2; ++ly) {
            float2 a  = tabp[ly*4+0]; ry_reg<2>(st, splat4(a.x),  splat4(a.y));
            float2 z  = tabp[ly*4+1]; rz_reg<2>(st, z.x, z.y);
            float2 a2 = tabp[ly*4+2]; ry_reg<1>(st, splat4(a2.x), splat4(a2.y));
            float2 z2 = tabp[ly*4+3]; rz_reg<1>(st, z2.x, z2.y);
            cnot_st(st);
        }
    } else {
#pragma unroll
        for (int ly = 1; ly >= 0; --ly) {
            cnot_st(st);
            float2 z2 = tabp[ly*4+3]; rz_reg<1>(st, z2.x, -z2.y);
            float2 a2 = tabp[ly*4+2]; ry_reg<1>(st, splat4(a2.x), splat4(-a2.y));
            float2 z  = tabp[ly*4+1]; rz_reg<2>(st, z.x, -z.y);
            float2 a  = tabp[ly*4+0]; ry_reg<2>(st, splat4(a.x),  splat4(-a.y));
        }
    }
}

// ---------------- fused kernel: round-2 MLP + two lockstep sims, grid=128 ----------------
__global__ void __launch_bounds__(256) k_all(
    const float* __restrict__ t, const float* __restrict__ z_t,
    const float* __restrict__ te_w1, const float* __restrict__ te_b1,
    const float* __restrict__ te_w2, const float* __restrict__ te_b2,
    const float* __restrict__ ip_w1, const float* __restrict__ ip_b1,
    const float* __restrict__ ip_w2, const float* __restrict__ ip_b2,
    const float* __restrict__ prep_p, const float* __restrict__ sig,
    const float* __restrict__ qff,
    const float* __restrict__ A_obs, const float* __restrict__ B_obs,
    const float* __restrict__ D_obs,
    const float* __restrict__ head_w, const float* __restrict__ head_b,
    float* __restrict__ out) {
    __shared__ float2 sbuf2[2][1024];   // exchange / obs, per half
    __shared__ float4 tabc2[2][64];
    __shared__ float4 tabs2[2][64];
    __shared__ float2 tabq[32];
    __shared__ float2 tabp[8];
    __shared__ float2 tabsig[4];
    __shared__ float part[2][28];
    __shared__ float emb[2][128];
    __shared__ float hb[2][128];
    __shared__ float cat[2][256];
    __shared__ float g1[2][256];

    const int tid  = threadIdx.x;
    const int lane = tid & 31;
    const int half = tid >> 7;
    const int htid = tid & 127;
    const int hwarp = htid >> 5;
    const int r0 = blockIdx.x * 2;
    const int b  = r0 + half;

    // ===== MLP phase (round-2 codegen, 2 rows per block) =====
    // stage A: sinusoidal embedding + copy z_t into cat
    {
        int row = half, i = htid;
        float tv = t[r0 + row];
        int ii = i & 63;
        float f = expf(-0.14391156831212787f * (float)ii);
        float a = tv * f;
        emb[row][i] = (i < 64) ? cosf(a) : sinf(a);
        cat[row][i] = z_t[(r0 + row) * 128 + i];
    }
    __syncthreads();

    // stage B: h = silu(te_w1 @ emb + te_b1)
    if (tid < 128) {
        int j = tid;
        float a0 = te_b1[j], a1 = a0;
        const float4* w4 = reinterpret_cast<const float4*>(te_w1 + j * 128);
#pragma unroll 8
        for (int k4 = 0; k4 < 32; ++k4) {
            float4 wv = w4[k4];
            float4 x0 = *reinterpret_cast<const float4*>(&emb[0][k4 * 4]);
            float4 x1 = *reinterpret_cast<const float4*>(&emb[1][k4 * 4]);
            a0 = fmaf(wv.x, x0.x, a0); a0 = fmaf(wv.y, x0.y, a0);
            a0 = fmaf(wv.z, x0.z, a0); a0 = fmaf(wv.w, x0.w, a0);
            a1 = fmaf(wv.x, x1.x, a1); a1 = fmaf(wv.y, x1.y, a1);
            a1 = fmaf(wv.z, x1.z, a1); a1 = fmaf(wv.w, x1.w, a1);
        }
        hb[0][j] = silu_f(a0); hb[1][j] = silu_f(a1);
    }
    __syncthreads();

    // stage C: t_emb2 = te_w2 @ h + te_b2 -> cat[., 128+j]
    if (tid < 128) {
        int j = tid;
        float a0 = te_b2[j], a1 = a0;
        const float4* w4 = reinterpret_cast<const float4*>(te_w2 + j * 128);
#pragma unroll 8
        for (int k4 = 0; k4 < 32; ++k4) {
            float4 wv = w4[k4];
            float4 x0 = *reinterpret_cast<const float4*>(&hb[0][k4 * 4]);
            float4 x1 = *reinterpret_cast<const float4*>(&hb[1][k4 * 4]);
            a0 = fmaf(wv.x, x0.x, a0); a0 = fmaf(wv.y, x0.y, a0);
            a0 = fmaf(wv.z, x0.z, a0); a0 = fmaf(wv.w, x0.w, a0);
            a1 = fmaf(wv.x, x1.x, a1); a1 = fmaf(wv.y, x1.y, a1);
            a1 = fmaf(wv.z, x1.z, a1); a1 = fmaf(wv.w, x1.w, a1);
        }
        cat[0][128 + j] = a0; cat[1][128 + j] = a1;
    }
    __syncthreads();

    // stage D: g1 = silu(ip_w1 @ cat + ip_b1)
    {
        int j = tid;
        float a0 = ip_b1[j], a1 = a0;
        const float4* w4 = reinterpret_cast<const float4*>(ip_w1 + j * 256);
#pragma unroll 8
        for (int k4 = 0; k4 < 64; ++k4) {
            float4 wv = w4[k4];
            float4 x0 = *reinterpret_cast<const float4*>(&cat[0][k4 * 4]);
            float4 x1 = *reinterpret_cast<const float4*>(&cat[1][k4 * 4]);
            a0 = fmaf(wv.x, x0.x, a0); a0 = fmaf(wv.y, x0.y, a0);
            a0 = fmaf(wv.z, x0.z, a0); a0 = fmaf(wv.w, x0.w, a0);
            a1 = fmaf(wv.x, x1.x, a1); a1 = fmaf(wv.y, x1.y, a1);
            a1 = fmaf(wv.z, x1.z, a1); a1 = fmaf(wv.w, x1.w, a1);
        }
        g1[0][j] = silu_f(a0); g1[1][j] = silu_f(a1);
    }
    __syncthreads();

    // stage E: ts = sigmoid(ip_w2 @ g1 + ip_b2) * 2pi  -> sincos tables directly
    {
        int j = tid;      // j = s*64 + g
        float a0 = ip_b2[j], a1 = a0;
        const float4* w4 = reinterpret_cast<const float4*>(ip_w2 + j * 256);
#pragma unroll 8
        for (int k4 = 0; k4 < 64; ++k4) {
            float4 wv = w4[k4];
            float4 x0 = *reinterpret_cast<const float4*>(&g1[0][k4 * 4]);
            float4 x1 = *reinterpret_cast<const float4*>(&g1[1][k4 * 4]);
            a0 = fmaf(wv.x, x0.x, a0); a0 = fmaf(wv.y, x0.y, a0);
            a0 = fmaf(wv.z, x0.z, a0); a0 = fmaf(wv.w, x0.w, a0);
            a1 = fmaf(wv.x, x1.x, a1); a1 = fmaf(wv.y, x1.y, a1);
            a1 = fmaf(wv.z, x1.z, a1); a1 = fmaf(wv.w, x1.w, a1);
        }
        int s = j >> 6, g = j & 63;
        float ang0 = TWO_PI_F / (1.f + expf(-a0));
        float ang1 = TWO_PI_F / (1.f + expf(-a1));
        float sn0, cc0, sn1, cc1;
        sincosf(ang0 * 0.5f, &sn0, &cc0);
        sincosf(ang1 * 0.5f, &sn1, &cc1);
        reinterpret_cast<float*>(tabc2[0])[g * 4 + s] = cc0;
        reinterpret_cast<float*>(tabs2[0])[g * 4 + s] = sn0;
        reinterpret_cast<float*>(tabc2[1])[g * 4 + s] = cc1;
        reinterpret_cast<float*>(tabs2[1])[g * 4 + s] = sn1;
    }
    // small tables (shared between halves — batch-independent)
    if (tid < 32)      { float sn, cc; sincosf(qff[tid] * 0.5f, &sn, &cc); tabq[tid] = make_float2(cc, sn); }
    else if (tid < 40) { int q = tid - 32; float sn, cc; sincosf(prep_p[q] * 0.5f, &sn, &cc); tabp[q] = make_float2(cc, sn); }
    else if (tid < 44) { int q = tid - 40; float sn, cc; sincosf(sig[q], &sn, &cc); tabsig[q] = make_float2(cc, sn); }
    __syncthreads();

    // ===== sim phase: two elements in lockstep (warps 0-3 / 4-7) =====
    float2* sbuf = sbuf2[half];
    const float4* tabc = tabc2[half];
    const float4* tabs = tabs2[half];

    float2 st[8];
#pragma unroll
    for (int r = 0; r < 8; ++r) st[r] = make_float2(0.f, 0.f);
    if (htid == 0) st[0].x = 1.f;

    { float2 p = tabsig[0]; pcphase_g(st, p.x, p.y); }
#pragma unroll 1
    for (int k = 0; k < 3; ++k) {
        do_prepare(st, tabp, false);
        run_sim14_2l(st, lane, htid, sbuf, tabc, tabs, (k & 1) != 0);
        do_prepare(st, tabp, true);
        float2 p = tabsig[k + 1];
        pcphase_g(st, p.x, p.y);
    }
    // final sim14 with qff params, 1 layer (uniform theta)
#pragma unroll 1
    for (int step = 0; step < 32; ++step) {
        float2 tq = tabq[step];
        apply_op(st, lane, htid, sbuf, c_OPC[step], c_OPT[step],
                 splat4(tq.x), splat4(tq.y));
    }

    // dump state to shared (swizzled) for expectation values
    __syncthreads();
#pragma unroll
    for (int r = 0; r < 8; ++r) {
        int n = (lane << 5) | (hwarp << 3) | r;
        sbuf[OIDX(n)] = st[r];
    }
    __syncthreads();

#pragma unroll 1
    for (int w = 0; w < 7; ++w) {
        const float* Aw = A_obs + w * 6;
        const float* Bw = B_obs + w * 6;
        const float* Dw = D_obs + w * 4;
        float d0 = 2.f * Dw[1], d1 = 2.f * Dw[2], d2 = 2.f * Dw[3];
        float a10 = Aw[0], b10 = Bw[0], a20 = Aw[1], b20 = Bw[1], a21 = Aw[2], b21 = Bw[2];
        float a30 = Aw[3], b30 = Bw[3], a31 = Aw[4], b31 = Bw[4], a32 = Aw[5], b32 = Bw[5];
        int b1 = 8 - w;
        int m1 = 1 << b1, m0 = m1 << 1;
        int lowmask = m1 - 1;
        float acc = 0.f;
#pragma unroll
        for (int it = 0; it < 2; ++it) {
            int gi = htid + it * 128;
            int n = ((gi & ~lowmask) << 2) | (gi & lowmask);
            float2 v0 = sbuf[OIDX(n)];
            float2 v1 = sbuf[OIDX(n + m1)];
            float2 v2 = sbuf[OIDX(n + m0)];
            float2 v3 = sbuf[OIDX(n + m0 + m1)];
            acc += d0 * (v0.x * v0.x + v0.y * v0.y);
            acc += d1 * (v1.x * v1.x + v1.y * v1.y);
            acc += d2 * (v2.x * v2.x + v2.y * v2.y);
#define CROSS(vi, vj, aa, bb) { \
            float pr = vi.x * vj.x + vi.y * vj.y; \
            float pim = vi.x * vj.y - vi.y * vj.x; \
            acc += 2.f * (pr * (aa) - pim * (bb)); }
            CROSS(v1, v0, a10, b10)
            CROSS(v2, v0, a20, b20)
            CROSS(v2, v1, a21, b21)
            CROSS(v3, v0, a30, b30)
            CROSS(v3, v1, a31, b31)
            CROSS(v3, v2, a32, b32)
#undef CROSS
        }
#pragma unroll
        for (int off = 16; off; off >>= 1) acc += __shfl_xor_sync(FULLMASK, acc, off);
        if (lane == 0) part[half][w * 4 + hwarp] = acc;
    }
    __syncthreads();

    // head: out[b][j] = sum_w e[w] * head_w[j*7+w] + head_b[j]
    {
        int j = htid;
        float o = head_b[j];
        const float* pp = part[half];
#pragma unroll
        for (int w = 0; w < 7; ++w) {
            float e = pp[w*4] + pp[w*4+1] + pp[w*4+2] + pp[w*4+3];
            o = fmaf(e, head_w[j * 7 + w], o);
        }
        out[b * 128 + j] = o;
    }
}

// ---------------- launch ----------------
extern "C" void kernel_launch(void* const* d_in, const int* in_sizes, int n_in,
                              void* d_out, int out_size) {
    const float* z_t    = (const float*)d_in[0];
    const float* t      = (const float*)d_in[1];
    const float* te_w1  = (const float*)d_in[2];
    const float* te_b1  = (const float*)d_in[3];
    const float* te_w2  = (const float*)d_in[4];
    const float* te_b2  = (const float*)d_in[5];
    const float* ip_w1  = (const float*)d_in[6];
    const float* ip_b1  = (const float*)d_in[7];
    const float* ip_w2  = (const float*)d_in[8];
    const float* ip_b2  = (const float*)d_in[9];
    const float* prep   = (const float*)d_in[10];
    const float* sig    = (const float*)d_in[11];
    const float* qff    = (const float*)d_in[12];
    const float* A_obs  = (const float*)d_in[13];
    const float* B_obs  = (const float*)d_in[14];
    const float* D_obs  = (const float*)d_in[15];
    const float* head_w = (const float*)d_in[16];
    const float* head_b = (const float*)d_in[17];
    float* out = (float*)d_out;

    k_all<<<128, 256>>>(t, z_t, te_w1, te_b1, te_w2, te_b2, ip_w1, ip_b1, ip_w2, ip_b2,
                        prep, sig, qff, A_obs, B_obs, D_obs, head_w, head_b, out);
}

// round 15
// speedup vs baseline: 2.0496x; 1.5831x over previous
#include <cuda_runtime.h>
#include <math.h>

#define FULLMASK 0xffffffffu
#define TWO_PI_F 6.2831853071795864f

// ---------------- scratch ----------------
__device__ float g_ts[256 * 256];   // ts angles, row b: [s*64 + g]

// ---------------- sim14 single-layer op schedule (32 ops) ----------------
__constant__ int c_OPC[32] = {
    -1,-1,-1,-1,-1,-1,-1,-1,
     7, 6, 5, 4, 3, 2, 1, 0,
    -1,-1,-1,-1,-1,-1,-1,-1,
     7, 0, 1, 2, 3, 4, 5, 6};
__constant__ int c_OPT[32] = {
     0, 1, 2, 3, 4, 5, 6, 7,
     0, 7, 6, 5, 4, 3, 2, 1,
     0, 1, 2, 3, 4, 5, 6, 7,
     6, 7, 0, 1, 2, 3, 4, 5};

// ---------------- helpers ----------------
__device__ __forceinline__ float g4(float4 v, int i) {
    return (i == 0) ? v.x : (i == 1) ? v.y : (i == 2) ? v.z : v.w;
}
__device__ __forceinline__ float4 splat4(float v) { return make_float4(v, v, v, v); }
__device__ __forceinline__ float silu_f(float x) { return x * (1.f / (1.f + expf(-x))); }

// per-half barrier: syncs the 128 threads of one half (barrier id 1 or 2)
__device__ __forceinline__ void hbar(int id) {
    asm volatile("bar.sync %0, 128;" :: "r"(id) : "memory");
}

// State layout (4 warps per element; two independent elements per 256-thread block):
//   htid = tid & 127 within the element's half.
//   flat index n (10 bits): bit9..bit5 = wires 0..4 (lane bits 4..0),
//   bit4 = wire5 (htid bit 6), bit3 = wire6 (htid bit 5),
//   bit2 = wire7 (reg M=4), bit1 = wire8/anc0 (M=2), bit0 = wire9/anc1 (M=1).
//   Each thread holds 8 float2 (r = bits 2..0). select index s = r & 3.
#define OIDX(n) ((n) ^ (((n) >> 5) & 31))

// RY on a lane-bit wire
__device__ __forceinline__ void ry_lane(float2 (&st)[8], int lmask, int lb, int lane,
                                        float4 c, float4 s) {
    float sg = ((lane >> lb) & 1) ? 1.f : -1.f;
    float4 sv = make_float4(g4(s,0)*sg, g4(s,1)*sg, g4(s,2)*sg, g4(s,3)*sg);
#pragma unroll
    for (int r = 0; r < 8; ++r) {
        float ox = __shfl_xor_sync(FULLMASK, st[r].x, lmask);
        float oy = __shfl_xor_sync(FULLMASK, st[r].y, lmask);
        float pc = g4(c, r & 3), ps = g4(sv, r & 3);
        st[r].x = fmaf(pc, st[r].x, ps * ox);
        st[r].y = fmaf(pc, st[r].y, ps * oy);
    }
}

// RY on a reg-bit wire (mask M in {4,2,1})
template <int M>
__device__ __forceinline__ void ry_reg(float2 (&st)[8], float4 c, float4 s) {
#pragma unroll
    for (int r = 0; r < 8; ++r) {
        if ((r & M) == 0) {
            const int r1 = r | M;
            float pc = g4(c, r & 3), ps = g4(s, r & 3);
            float ax = st[r].x, ay = st[r].y, bx = st[r1].x, by = st[r1].y;
            st[r].x = fmaf(pc, ax, -ps * bx);
            st[r].y = fmaf(pc, ay, -ps * by);
            st[r1].x = fmaf(ps, ax, pc * bx);
            st[r1].y = fmaf(ps, ay, pc * by);
        }
    }
}

// CRX with target on a lane-bit wire
__device__ __forceinline__ void crx_lane(float2 (&st)[8], int tmask,
                                         bool actBase, int crm,
                                         float4 c, float4 s) {
#pragma unroll
    for (int r = 0; r < 8; ++r) {
        float ox = __shfl_xor_sync(FULLMASK, st[r].x, tmask);
        float oy = __shfl_xor_sync(FULLMASK, st[r].y, tmask);
        bool act = actBase && (crm == 0 || (r & crm) != 0);
        float pc = g4(c, r & 3), ps = g4(s, r & 3);
        float nx = fmaf(pc, st[r].x, ps * oy);
        float ny = fmaf(pc, st[r].y, -ps * ox);
        if (act) { st[r].x = nx; st[r].y = ny; }
    }
}

// CRX with target on a reg-bit wire (mask M)
template <int M>
__device__ __forceinline__ void crx_reg(float2 (&st)[8], bool actBase, int crm,
                                        float4 c, float4 s) {
#pragma unroll
    for (int r = 0; r < 8; ++r) {
        if ((r & M) == 0) {
            const int r1 = r | M;
            bool act = actBase && (crm == 0 || (r & crm) != 0);
            float pc = g4(c, r & 3), ps = g4(s, r & 3);
            float ax = st[r].x, ay = st[r].y, bx = st[r1].x, by = st[r1].y;
            float n0x = fmaf(pc, ax, ps * by);
            float n0y = fmaf(pc, ay, -ps * bx);
            float n1x = fmaf(pc, bx, ps * ay);
            float n1y = fmaf(pc, by, -ps * ax);
            if (act) { st[r] = make_float2(n0x, n0y); st[r1] = make_float2(n1x, n1y); }
        }
    }
}

// Op targeting a warp bit: per-half smem exchange with per-half named barrier.
// xm = 64 (w5) or 32 (w6); bid = half+1.
__device__ __forceinline__ void warp_op(float2 (&st)[8], float2* sbuf,
                                        int htid, int bid, int xm, bool isRY,
                                        bool actBase, int crm, float4 c, float4 s) {
    hbar(bid);
#pragma unroll
    for (int r = 0; r < 8; ++r) sbuf[r * 128 + htid] = st[r];
    hbar(bid);
    const int p = htid ^ xm;
    const float sg = (htid & xm) ? 1.f : -1.f;
#pragma unroll
    for (int r = 0; r < 8; ++r) {
        float2 o = sbuf[r * 128 + p];
        float pc = g4(c, r & 3), ps = g4(s, r & 3);
        if (isRY) {
            float pss = sg * ps;
            st[r].x = fmaf(pc, st[r].x, pss * o.x);
            st[r].y = fmaf(pc, st[r].y, pss * o.y);
        } else {
            bool act = actBase && (crm == 0 || (r & crm) != 0);
            float nx = fmaf(pc, st[r].x, ps * o.y);
            float ny = fmaf(pc, st[r].y, -ps * o.x);
            if (act) { st[r].x = nx; st[r].y = ny; }
        }
    }
}

// RZ on a reg-bit wire (ancilla)
template <int M>
__device__ __forceinline__ void rz_reg(float2 (&st)[8], float c, float s) {
#pragma unroll
    for (int r = 0; r < 8; ++r) {
        float ss = (r & M) ? s : -s;
        float x = st[r].x, y = st[r].y;
        st[r].x = fmaf(c, x, -ss * y);
        st[r].y = fmaf(c, y, ss * x);
    }
}

__device__ __forceinline__ void cnot_st(float2 (&st)[8]) {
#pragma unroll
    for (int r = 0; r < 8; ++r) {
        if ((r & 3) == 2) { float2 tmp = st[r]; st[r] = st[r | 1]; st[r | 1] = tmp; }
    }
}

__device__ __forceinline__ void pcphase_g(float2 (&st)[8], float cphi, float sphi) {
#pragma unroll
    for (int r = 0; r < 8; ++r) {
        float ss = ((r & 3) == 0) ? sphi : -sphi;
        float x = st[r].x, y = st[r].y;
        st[r].x = fmaf(cphi, x, -ss * y);
        st[r].y = fmaf(cphi, y, ss * x);
    }
}

__device__ __forceinline__ void apply_op(float2 (&st)[8], int lane, int htid, int bid,
                                         float2* sbuf,
                                         int cw, int tw, float4 c, float4 s) {
    if (cw < 0) {  // RY
        if (tw < 5)       ry_lane(st, 1 << (4 - tw), 4 - tw, lane, c, s);
        else if (tw == 5) warp_op(st, sbuf, htid, bid, 64, true, true, 0, c, s);
        else if (tw == 6) warp_op(st, sbuf, htid, bid, 32, true, true, 0, c, s);
        else              ry_reg<4>(st, c, s);
    } else {       // CRX
        bool actBase; int crm = 0;
        if (cw < 5)       actBase = ((lane >> (4 - cw)) & 1) != 0;
        else if (cw == 5) actBase = ((htid >> 6) & 1) != 0;
        else if (cw == 6) actBase = ((htid >> 5) & 1) != 0;
        else { actBase = true; crm = 4; }
        if (tw < 5)       crx_lane(st, 1 << (4 - tw), actBase, crm, c, s);
        else if (tw == 5) warp_op(st, sbuf, htid, bid, 64, false, actBase, crm, c, s);
        else if (tw == 6) warp_op(st, sbuf, htid, bid, 32, false, actBase, crm, c, s);
        else              crx_reg<4>(st, actBase, crm, c, s);
    }
}

// sim14 with 2 layers (compact loop, runtime dispatch)
__device__ __forceinline__ void run_sim14_2l(float2 (&st)[8], int lane, int htid, int bid,
                                             float2* sbuf,
                                             const float4* tabc, const float4* tabs,
                                             bool adj) {
    if (!adj) {
#pragma unroll 1
        for (int step = 0; step < 64; ++step) {
            int o = step & 31;
            float4 c = tabc[step];
            float4 s = tabs[step];
            apply_op(st, lane, htid, bid, sbuf, c_OPC[o], c_OPT[o], c, s);
        }
    } else {
#pragma unroll 1
        for (int step = 63; step >= 0; --step) {
            int o = step & 31;
            float4 c = tabc[step];
            float4 s0 = tabs[step];
            float4 s = make_float4(-s0.x, -s0.y, -s0.z, -s0.w);
            apply_op(st, lane, htid, bid, sbuf, c_OPC[o], c_OPT[o], c, s);
        }
    }
}

__device__ __forceinline__ void do_prepare(float2 (&st)[8], const float2* tabp, bool adj) {
    if (!adj) {
#pragma unroll
        for (int ly = 0; ly < 2; ++ly) {
            float2 a  = tabp[ly*4+0]; ry_reg<2>(st, splat4(a.x),  splat4(a.y));
            float2 z  = tabp[ly*4+1]; rz_reg<2>(st, z.x, z.y);
            float2 a2 = tabp[ly*4+2]; ry_reg<1>(st, splat4(a2.x), splat4(a2.y));
            float2 z2 = tabp[ly*4+3]; rz_reg<1>(st, z2.x, z2.y);
            cnot_st(st);
        }
    } else {
#pragma unroll
        for (int ly = 1; ly >= 0; --ly) {
            cnot_st(st);
            float2 z2 = tabp[ly*4+3]; rz_reg<1>(st, z2.x, -z2.y);
            float2 a2 = tabp[ly*4+2]; ry_reg<1>(st, splat4(a2.x), splat4(-a2.y));
            float2 z  = tabp[ly*4+1]; rz_reg<2>(st, z.x, -z.y);
            float2 a  = tabp[ly*4+0]; ry_reg<2>(st, splat4(a.x),  splat4(-a.y));
        }
    }
}

// ---------------- simulate kernel: 2 independent elements per 256-thread block ----------------
// grid = 128 (single wave on 148 SMs). Halves never share a barrier.
__global__ void __launch_bounds__(256) k_sim(
    const float* __restrict__ prep_p, const float* __restrict__ sig,
    const float* __restrict__ qff,
    const float* __restrict__ A_obs, const float* __restrict__ B_obs,
    const float* __restrict__ D_obs,
    const float* __restrict__ head_w, const float* __restrict__ head_b,
    float* __restrict__ out) {
    __shared__ float2 sbuf2[2][1024];   // per-half exchange / obs
    __shared__ float4 tabc2[2][64];
    __shared__ float4 tabs2[2][64];
    __shared__ float2 tabq2[2][32];
    __shared__ float2 tabp2[2][8];
    __shared__ float2 tabsig2[2][4];
    __shared__ float part2[2][28];

    const int tid   = threadIdx.x;
    const int lane  = tid & 31;
    const int half  = tid >> 7;
    const int htid  = tid & 127;
    const int hwarp = htid >> 5;
    const int bid   = half + 1;          // named barrier id for this half
    const int b     = blockIdx.x * 2 + half;
    const float* tsr = g_ts + b * 256;

    // per-half prologue (no cross-half dependencies)
    if (htid < 64) {
        float c0,s0,c1,s1,c2,s2,c3,s3;
        sincosf(tsr[htid]       * 0.5f, &s0, &c0);
        sincosf(tsr[64 + htid]  * 0.5f, &s1, &c1);
        sincosf(tsr[128 + htid] * 0.5f, &s2, &c2);
        sincosf(tsr[192 + htid] * 0.5f, &s3, &c3);
        tabc2[half][htid] = make_float4(c0, c1, c2, c3);
        tabs2[half][htid] = make_float4(s0, s1, s2, s3);
    } else if (htid < 96) {
        int q = htid - 64;
        float sn, cc; sincosf(qff[q] * 0.5f, &sn, &cc);
        tabq2[half][q] = make_float2(cc, sn);
    } else if (htid < 104) {
        int q = htid - 96;
        float sn, cc; sincosf(prep_p[q] * 0.5f, &sn, &cc);
        tabp2[half][q] = make_float2(cc, sn);
    } else if (htid < 108) {
        int q = htid - 104;
        float sn, cc; sincosf(sig[q], &sn, &cc);
        tabsig2[half][q] = make_float2(cc, sn);
    }
    hbar(bid);

    float2* sbuf = sbuf2[half];
    const float4* tabc = tabc2[half];
    const float4* tabs = tabs2[half];
    const float2* tabq = tabq2[half];
    const float2* tabp = tabp2[half];
    const float2* tabsig = tabsig2[half];

    float2 st[8];
#pragma unroll
    for (int r = 0; r < 8; ++r) st[r] = make_float2(0.f, 0.f);
    if (htid == 0) st[0].x = 1.f;

    { float2 p = tabsig[0]; pcphase_g(st, p.x, p.y); }
#pragma unroll 1
    for (int k = 0; k < 3; ++k) {
        do_prepare(st, tabp, false);
        run_sim14_2l(st, lane, htid, bid, sbuf, tabc, tabs, (k & 1) != 0);
        do_prepare(st, tabp, true);
        float2 p = tabsig[k + 1];
        pcphase_g(st, p.x, p.y);
    }
    // final sim14 with qff params, 1 layer (uniform theta)
#pragma unroll 1
    for (int step = 0; step < 32; ++step) {
        float2 tq = tabq[step];
        apply_op(st, lane, htid, bid, sbuf, c_OPC[step], c_OPT[step],
                 splat4(tq.x), splat4(tq.y));
    }

    // dump state to shared (swizzled) for expectation values
    hbar(bid);
#pragma unroll
    for (int r = 0; r < 8; ++r) {
        int n = (lane << 5) | (hwarp << 3) | r;
        sbuf[OIDX(n)] = st[r];
    }
    hbar(bid);

#pragma unroll 1
    for (int w = 0; w < 7; ++w) {
        const float* Aw = A_obs + w * 6;
        const float* Bw = B_obs + w * 6;
        const float* Dw = D_obs + w * 4;
        float d0 = 2.f * Dw[1], d1 = 2.f * Dw[2], d2 = 2.f * Dw[3];
        float a10 = Aw[0], b10 = Bw[0], a20 = Aw[1], b20 = Bw[1], a21 = Aw[2], b21 = Bw[2];
        float a30 = Aw[3], b30 = Bw[3], a31 = Aw[4], b31 = Bw[4], a32 = Aw[5], b32 = Bw[5];
        int b1 = 8 - w;
        int m1 = 1 << b1, m0 = m1 << 1;
        int lowmask = m1 - 1;
        float acc = 0.f;
#pragma unroll
        for (int it = 0; it < 2; ++it) {
            int gi = htid + it * 128;
            int n = ((gi & ~lowmask) << 2) | (gi & lowmask);
            float2 v0 = sbuf[OIDX(n)];
            float2 v1 = sbuf[OIDX(n + m1)];
            float2 v2 = sbuf[OIDX(n + m0)];
            float2 v3 = sbuf[OIDX(n + m0 + m1)];
            acc += d0 * (v0.x * v0.x + v0.y * v0.y);
            acc += d1 * (v1.x * v1.x + v1.y * v1.y);
            acc += d2 * (v2.x * v2.x + v2.y * v2.y);
#define CROSS(vi, vj, aa, bb) { \
            float pr = vi.x * vj.x + vi.y * vj.y; \
            float pim = vi.x * vj.y - vi.y * vj.x; \
            acc += 2.f * (pr * (aa) - pim * (bb)); }
            CROSS(v1, v0, a10, b10)
            CROSS(v2, v0, a20, b20)
            CROSS(v2, v1, a21, b21)
            CROSS(v3, v0, a30, b30)
            CROSS(v3, v1, a31, b31)
            CROSS(v3, v2, a32, b32)
#undef CROSS
        }
#pragma unroll
        for (int off = 16; off; off >>= 1) acc += __shfl_xor_sync(FULLMASK, acc, off);
        if (lane == 0) part2[half][w * 4 + hwarp] = acc;
    }
    hbar(bid);

    // head: out[b][j] = sum_w e[w] * head_w[j*7+w] + head_b[j]
    {
        int j = htid;
        float o = head_b[j];
        const float* pp = part2[half];
#pragma unroll
        for (int w = 0; w < 7; ++w) {
            float e = pp[w*4] + pp[w*4+1] + pp[w*4+2] + pp[w*4+3];
            o = fmaf(e, head_w[j * 7 + w], o);
        }
        out[b * 128 + j] = o;
    }
}

// ---------------- fused MLP kernel: 2 batch rows per block (round-2 exact) ----------------
__global__ void __launch_bounds__(256) k_mlp(
    const float* __restrict__ t, const float* __restrict__ z_t,
    const float* __restrict__ te_w1, const float* __restrict__ te_b1,
    const float* __restrict__ te_w2, const float* __restrict__ te_b2,
    const float* __restrict__ ip_w1, const float* __restrict__ ip_b1,
    const float* __restrict__ ip_w2, const float* __restrict__ ip_b2) {
    __shared__ float emb[2][128];
    __shared__ float hb[2][128];
    __shared__ float cat[2][256];
    __shared__ float g1[2][256];
    const int tid = threadIdx.x;
    const int r0 = blockIdx.x * 2;

    // stage A: sinusoidal embedding + copy z_t into cat
    {
        int row = tid >> 7, i = tid & 127;
        float tv = t[r0 + row];
        int ii = i & 63;
        float f = expf(-0.14391156831212787f * (float)ii);
        float a = tv * f;
        emb[row][i] = (i < 64) ? cosf(a) : sinf(a);
        cat[row][i] = z_t[(r0 + row) * 128 + i];
    }
    __syncthreads();

    // stage B: h = silu(te_w1 @ emb + te_b1)
    if (tid < 128) {
        int j = tid;
        float a0 = te_b1[j], a1 = a0;
        const float4* w4 = reinterpret_cast<const float4*>(te_w1 + j * 128);
#pragma unroll 8
        for (int k4 = 0; k4 < 32; ++k4) {
            float4 wv = w4[k4];
            float4 x0 = *reinterpret_cast<const float4*>(&emb[0][k4 * 4]);
            float4 x1 = *reinterpret_cast<const float4*>(&emb[1][k4 * 4]);
            a0 = fmaf(wv.x, x0.x, a0); a0 = fmaf(wv.y, x0.y, a0);
            a0 = fmaf(wv.z, x0.z, a0); a0 = fmaf(wv.w, x0.w, a0);
            a1 = fmaf(wv.x, x1.x, a1); a1 = fmaf(wv.y, x1.y, a1);
            a1 = fmaf(wv.z, x1.z, a1); a1 = fmaf(wv.w, x1.w, a1);
        }
        hb[0][j] = silu_f(a0); hb[1][j] = silu_f(a1);
    }
    __syncthreads();

    // stage C: t_emb2 = te_w2 @ h + te_b2 -> cat[., 128+j]
    if (tid < 128) {
        int j = tid;
        float a0 = te_b2[j], a1 = a0;
        const float4* w4 = reinterpret_cast<const float4*>(te_w2 + j * 128);
#pragma unroll 8
        for (int k4 = 0; k4 < 32; ++k4) {
            float4 wv = w4[k4];
            float4 x0 = *reinterpret_cast<const float4*>(&hb[0][k4 * 4]);
            float4 x1 = *reinterpret_cast<const float4*>(&hb[1][k4 * 4]);
            a0 = fmaf(wv.x, x0.x, a0); a0 = fmaf(wv.y, x0.y, a0);
            a0 = fmaf(wv.z, x0.z, a0); a0 = fmaf(wv.w, x0.w, a0);
            a1 = fmaf(wv.x, x1.x, a1); a1 = fmaf(wv.y, x1.y, a1);
            a1 = fmaf(wv.z, x1.z, a1); a1 = fmaf(wv.w, x1.w, a1);
        }
        cat[0][128 + j] = a0; cat[1][128 + j] = a1;
    }
    __syncthreads();

    // stage D: g1 = silu(ip_w1 @ cat + ip_b1)
    {
        int j = tid;
        float a0 = ip_b1[j], a1 = a0;
        const float4* w4 = reinterpret_cast<const float4*>(ip_w1 + j * 256);
#pragma unroll 8
        for (int k4 = 0; k4 < 64; ++k4) {
            float4 wv = w4[k4];
            float4 x0 = *reinterpret_cast<const float4*>(&cat[0][k4 * 4]);
            float4 x1 = *reinterpret_cast<const float4*>(&cat[1][k4 * 4]);
            a0 = fmaf(wv.x, x0.x, a0); a0 = fmaf(wv.y, x0.y, a0);
            a0 = fmaf(wv.z, x0.z, a0); a0 = fmaf(wv.w, x0.w, a0);
            a1 = fmaf(wv.x, x1.x, a1); a1 = fmaf(wv.y, x1.y, a1);
            a1 = fmaf(wv.z, x1.z, a1); a1 = fmaf(wv.w, x1.w, a1);
        }
        g1[0][j] = silu_f(a0); g1[1][j] = silu_f(a1);
    }
    __syncthreads();

    // stage E: ts = sigmoid(ip_w2 @ g1 + ip_b2) * 2pi
    {
        int j = tid;
        float a0 = ip_b2[j], a1 = a0;
        const float4* w4 = reinterpret_cast<const float4*>(ip_w2 + j * 256);
#pragma unroll 8
        for (int k4 = 0; k4 < 64; ++k4) {
            float4 wv = w4[k4];
            float4 x0 = *reinterpret_cast<const float4*>(&g1[0][k4 * 4]);
            float4 x1 = *reinterpret_cast<const float4*>(&g1[1][k4 * 4]);
            a0 = fmaf(wv.x, x0.x, a0); a0 = fmaf(wv.y, x0.y, a0);
            a0 = fmaf(wv.z, x0.z, a0); a0 = fmaf(wv.w, x0.w, a0);
            a1 = fmaf(wv.x, x1.x, a1); a1 = fmaf(wv.y, x1.y, a1);
            a1 = fmaf(wv.z, x1.z, a1); a1 = fmaf(wv.w, x1.w, a1);
        }
        g_ts[r0 * 256 + j]       = TWO_PI_F / (1.f + expf(-a0));
        g_ts[(r0 + 1) * 256 + j] = TWO_PI_F / (1.f + expf(-a1));
    }
}

// ---------------- launch ----------------
extern "C" void kernel_launch(void* const* d_in, const int* in_sizes, int n_in,
                              void* d_out, int out_size) {
    const float* z_t    = (const float*)d_in[0];
    const float* t      = (const float*)d_in[1];
    const float* te_w1  = (const float*)d_in[2];
    const float* te_b1  = (const float*)d_in[3];
    const float* te_w2  = (const float*)d_in[4];
    const float* te_b2  = (const float*)d_in[5];
    const float* ip_w1  = (const float*)d_in[6];
    const float* ip_b1  = (const float*)d_in[7];
    const float* ip_w2  = (const float*)d_in[8];
    const float* ip_b2  = (const float*)d_in[9];
    const float* prep   = (const float*)d_in[10];
    const float* sig    = (const float*)d_in[11];
    const float* qff    = (const float*)d_in[12];
    const float* A_obs  = (const float*)d_in[13];
    const float* B_obs  = (const float*)d_in[14];
    const float* D_obs  = (const float*)d_in[15];
    const float* head_w = (const float*)d_in[16];
    const float* head_b = (const float*)d_in[17];
    float* out = (float*)d_out;

    k_mlp<<<128, 256>>>(t, z_t, te_w1, te_b1, te_w2, te_b2, ip_w1, ip_b1, ip_w2, ip_b2);
    k_sim<<<128, 256>>>(prep, sig, qff, A_obs, B_obs, D_obs, head_w, head_b, out);
}

// round 16
// speedup vs baseline: 2.1285x; 1.0385x over previous
#include <cuda_runtime.h>
#include <math.h>

#define FULLMASK 0xffffffffu
#define TWO_PI_F 6.2831853071795864f

// ---------------- scratch ----------------
__device__ float g_ts[256 * 256];   // ts angles, row b: [s*64 + g]

// ---------------- sim14 single-layer op schedule (32 ops) ----------------
__constant__ int c_OPC[32] = {
    -1,-1,-1,-1,-1,-1,-1,-1,
     7, 6, 5, 4, 3, 2, 1, 0,
    -1,-1,-1,-1,-1,-1,-1,-1,
     7, 0, 1, 2, 3, 4, 5, 6};
__constant__ int c_OPT[32] = {
     0, 1, 2, 3, 4, 5, 6, 7,
     0, 7, 6, 5, 4, 3, 2, 1,
     0, 1, 2, 3, 4, 5, 6, 7,
     6, 7, 0, 1, 2, 3, 4, 5};

// ---------------- helpers ----------------
__device__ __forceinline__ float silu_f(float x) { return x * (1.f / (1.f + expf(-x))); }

// State layout (4 warps per batch element, 128 threads; warp index = ancilla s):
//   flat index n (10 bits): bit9..bit5 = wires 0..4 (lane bits 4..0),
//   bit4 = wire5 (reg M=4), bit3 = wire6 (reg M=2), bit2 = wire7 (reg M=1),
//   bit1 = wire8/anc0 (tid bit 6), bit0 = wire9/anc1 (tid bit 5).
//   Each thread holds 8 float2: n = (lane<<5) | (r<<2) | warp.
#define OIDX(n) ((n) ^ (((n) >> 5) & 31))

// RY on a lane-bit wire (scalar coeffs)
__device__ __forceinline__ void ry_lane(float2 (&st)[8], int lmask, int lb, int lane,
                                        float c, float s) {
    float sv = ((lane >> lb) & 1) ? s : -s;
#pragma unroll
    for (int r = 0; r < 8; ++r) {
        float ox = __shfl_xor_sync(FULLMASK, st[r].x, lmask);
        float oy = __shfl_xor_sync(FULLMASK, st[r].y, lmask);
        st[r].x = fmaf(c, st[r].x, sv * ox);
        st[r].y = fmaf(c, st[r].y, sv * oy);
    }
}

// RY on a reg-bit wire (mask M in {4,2,1})
template <int M>
__device__ __forceinline__ void ry_reg(float2 (&st)[8], float c, float s) {
#pragma unroll
    for (int r = 0; r < 8; ++r) {
        if ((r & M) == 0) {
            const int r1 = r | M;
            float ax = st[r].x, ay = st[r].y, bx = st[r1].x, by = st[r1].y;
            st[r].x = fmaf(c, ax, -s * bx);
            st[r].y = fmaf(c, ay, -s * by);
            st[r1].x = fmaf(s, ax, c * bx);
            st[r1].y = fmaf(s, ay, c * by);
        }
    }
}

// CRX target=lane wire, control=lane bit (act uniform over r; predicated store)
__device__ __forceinline__ void crx_lane(float2 (&st)[8], int tmask, bool act,
                                         float c, float s) {
#pragma unroll
    for (int r = 0; r < 8; ++r) {
        float ox = __shfl_xor_sync(FULLMASK, st[r].x, tmask);
        float oy = __shfl_xor_sync(FULLMASK, st[r].y, tmask);
        float nx = fmaf(c, st[r].x, s * oy);
        float ny = fmaf(c, st[r].y, -s * ox);
        if (act) { st[r].x = nx; st[r].y = ny; }
    }
}

// CRX target=reg wire M, control=lane bit
template <int M>
__device__ __forceinline__ void crx_reg(float2 (&st)[8], bool act, float c, float s) {
#pragma unroll
    for (int r = 0; r < 8; ++r) {
        if ((r & M) == 0) {
            const int r1 = r | M;
            float ax = st[r].x, ay = st[r].y, bx = st[r1].x, by = st[r1].y;
            float n0x = fmaf(c, ax, s * by);
            float n0y = fmaf(c, ay, -s * bx);
            float n1x = fmaf(c, bx, s * ay);
            float n1y = fmaf(c, by, -s * ax);
            if (act) { st[r] = make_float2(n0x, n0y); st[r1] = make_float2(n1x, n1y); }
        }
    }
}

// CRX target=lane wire, control=reg bit CRM (compile-time skip; uniform over lanes)
template <int CRM>
__device__ __forceinline__ void crx_lane_rc(float2 (&st)[8], int tmask, float c, float s) {
#pragma unroll
    for (int r = 0; r < 8; ++r) {
        if ((r & CRM) != 0) {
            float ox = __shfl_xor_sync(FULLMASK, st[r].x, tmask);
            float oy = __shfl_xor_sync(FULLMASK, st[r].y, tmask);
            st[r].x = fmaf(c, st[r].x, s * oy);
            st[r].y = fmaf(c, st[r].y, -s * ox);
        }
    }
}

// CRX target=reg wire M, control=reg bit CRM (compile-time skip)
template <int M, int CRM>
__device__ __forceinline__ void crx_reg_rc(float2 (&st)[8], float c, float s) {
#pragma unroll
    for (int r = 0; r < 8; ++r) {
        if ((r & M) == 0 && (r & CRM) != 0) {
            const int r1 = r | M;
            float ax = st[r].x, ay = st[r].y, bx = st[r1].x, by = st[r1].y;
            st[r].x  = fmaf(c, ax, s * by);
            st[r].y  = fmaf(c, ay, -s * bx);
            st[r1].x = fmaf(c, bx, s * ay);
            st[r1].y = fmaf(c, by, -s * ax);
        }
    }
}

// warp-uniform diagonal: v *= (c + i*ss)
__device__ __forceinline__ void rz_w(float2 (&st)[8], float c, float ss) {
#pragma unroll
    for (int r = 0; r < 8; ++r) {
        float x = st[r].x, y = st[r].y;
        st[r].x = fmaf(c, x, -ss * y);
        st[r].y = fmaf(c, y, ss * x);
    }
}

// RY on a warp bit (xm = 64 for w8, 32 for w9): smem exchange
__device__ __forceinline__ void prep_ry(float2 (&st)[8], float2* sbuf, int tid,
                                        int xm, float c, float s) {
    __syncthreads();
#pragma unroll
    for (int r = 0; r < 8; ++r) sbuf[r * 128 + tid] = st[r];
    __syncthreads();
    const int p = tid ^ xm;
    const float sg = (tid & xm) ? s : -s;
#pragma unroll
    for (int r = 0; r < 8; ++r) {
        float2 o = sbuf[r * 128 + p];
        st[r].x = fmaf(c, st[r].x, sg * o.x);
        st[r].y = fmaf(c, st[r].y, sg * o.y);
    }
}

// CNOT(control=w8, target=w9): warps 2<->3 swap
__device__ __forceinline__ void cnot_w(float2 (&st)[8], float2* sbuf, int tid) {
    __syncthreads();
#pragma unroll
    for (int r = 0; r < 8; ++r) sbuf[r * 128 + tid] = st[r];
    __syncthreads();
    if (tid & 64) {
        const int p = tid ^ 32;
#pragma unroll
        for (int r = 0; r < 8; ++r) st[r] = sbuf[r * 128 + p];
    }
}

__device__ __forceinline__ void apply_op(float2 (&st)[8], int lane,
                                         int cw, int tw, float c, float s) {
    if (cw < 0) {  // RY
        if (tw < 5)       ry_lane(st, 1 << (4 - tw), 4 - tw, lane, c, s);
        else if (tw == 5) ry_reg<4>(st, c, s);
        else if (tw == 6) ry_reg<2>(st, c, s);
        else              ry_reg<1>(st, c, s);
    } else if (cw < 5) {   // lane control
        bool act = ((lane >> (4 - cw)) & 1) != 0;
        if (tw < 5)       crx_lane(st, 1 << (4 - tw), act, c, s);
        else if (tw == 5) crx_reg<4>(st, act, c, s);
        else if (tw == 6) crx_reg<2>(st, act, c, s);
        else              crx_reg<1>(st, act, c, s);
    } else if (cw == 5) {  // control = reg bit 4
        if (tw == 6)      crx_reg_rc<2, 4>(st, c, s);        // (5,6)
        else              crx_lane_rc<4>(st, 1, c, s);       // (5,4): lane bit 0
    } else if (cw == 6) {  // control = reg bit 2
        if (tw == 7)      crx_reg_rc<1, 2>(st, c, s);        // (6,7)
        else              crx_reg_rc<4, 2>(st, c, s);        // (6,5)
    } else {               // cw == 7, control = reg bit 1
        if (tw == 0)      crx_lane_rc<1>(st, 16, c, s);      // (7,0): lane bit 4
        else              crx_reg_rc<2, 1>(st, c, s);        // (7,6)
    }
}

// sim14 with 2 layers; per-warp scalar coefficients from tab[step*4 + warp]
__device__ __forceinline__ void run_sim14_2l(float2 (&st)[8], int lane, int warp,
                                             const float2* tab, bool adj) {
    if (!adj) {
#pragma unroll 1
        for (int step = 0; step < 64; ++step) {
            int o = step & 31;
            float2 cs = tab[step * 4 + warp];
            apply_op(st, lane, c_OPC[o], c_OPT[o], cs.x, cs.y);
        }
    } else {
#pragma unroll 1
        for (int step = 63; step >= 0; --step) {
            int o = step & 31;
            float2 cs = tab[step * 4 + warp];
            apply_op(st, lane, c_OPC[o], c_OPT[o], cs.x, -cs.y);
        }
    }
}

// prepare on ancilla wires 8,9 (warp bits)
__device__ __forceinline__ void do_prepare(float2 (&st)[8], float2* sbuf, int tid,
                                           const float2* tabp, bool adj) {
    if (!adj) {
#pragma unroll
        for (int ly = 0; ly < 2; ++ly) {
            float2 a  = tabp[ly*4+0]; prep_ry(st, sbuf, tid, 64, a.x, a.y);
            float2 z  = tabp[ly*4+1]; rz_w(st, z.x, (tid & 64) ? z.y : -z.y);
            float2 a2 = tabp[ly*4+2]; prep_ry(st, sbuf, tid, 32, a2.x, a2.y);
            float2 z2 = tabp[ly*4+3]; rz_w(st, z2.x, (tid & 32) ? z2.y : -z2.y);
            cnot_w(st, sbuf, tid);
        }
    } else {
#pragma unroll
        for (int ly = 1; ly >= 0; --ly) {
            cnot_w(st, sbuf, tid);
            float2 z2 = tabp[ly*4+3]; rz_w(st, z2.x, (tid & 32) ? -z2.y : z2.y);
            float2 a2 = tabp[ly*4+2]; prep_ry(st, sbuf, tid, 32, a2.x, -a2.y);
            float2 z  = tabp[ly*4+1]; rz_w(st, z.x, (tid & 64) ? -z.y : z.y);
            float2 a  = tabp[ly*4+0]; prep_ry(st, sbuf, tid, 64, a.x, -a.y);
        }
    }
}

// ---------------- simulate kernel: 4 warps per batch element, warp = ancilla s ----------------
__global__ void __launch_bounds__(128) k_sim(
    const float* __restrict__ prep_p, const float* __restrict__ sig,
    const float* __restrict__ qff,
    const float* __restrict__ A_obs, const float* __restrict__ B_obs,
    const float* __restrict__ D_obs,
    const float* __restrict__ head_w, const float* __restrict__ head_b,
    float* __restrict__ out) {
    __shared__ float2 sbuf[1024];     // exchange / obs (8r x 128tid)
    __shared__ float2 tabsel[256];    // [step*4 + s]
    __shared__ float2 tabq[32];
    __shared__ float2 tabp[8];
    __shared__ float2 tabsig[4];
    __shared__ float part[28];

    const int tid  = threadIdx.x;
    const int lane = tid & 31;
    const int warp = tid >> 5;
    const int b    = blockIdx.x;
    const float* tsr = g_ts + b * 256;

    // tables: tsr index i = s*64 + g -> tabsel[g*4 + s]
#pragma unroll
    for (int u = 0; u < 2; ++u) {
        int i = tid + u * 128;
        int s = i >> 6, g = i & 63;
        float sn, cc; sincosf(tsr[i] * 0.5f, &sn, &cc);
        tabsel[g * 4 + s] = make_float2(cc, sn);
    }
    if (tid < 32)      { float sn, cc; sincosf(qff[tid] * 0.5f, &sn, &cc); tabq[tid] = make_float2(cc, sn); }
    else if (tid < 40) { int q = tid - 32; float sn, cc; sincosf(prep_p[q] * 0.5f, &sn, &cc); tabp[q] = make_float2(cc, sn); }
    else if (tid < 44) { int q = tid - 40; float sn, cc; sincosf(sig[q], &sn, &cc); tabsig[q] = make_float2(cc, sn); }
    __syncthreads();

    float2 st[8];
#pragma unroll
    for (int r = 0; r < 8; ++r) st[r] = make_float2(0.f, 0.f);
    if (tid == 0) st[0].x = 1.f;

    // pcphase(sig[0]): warp 0 (anc=0) gets +phi
    { float2 p = tabsig[0]; rz_w(st, p.x, (warp == 0) ? p.y : -p.y); }
#pragma unroll 1
    for (int k = 0; k < 3; ++k) {
        do_prepare(st, sbuf, tid, tabp, false);
        run_sim14_2l(st, lane, warp, tabsel, (k & 1) != 0);
        do_prepare(st, sbuf, tid, tabp, true);
        float2 p = tabsig[k + 1];
        rz_w(st, p.x, (warp == 0) ? p.y : -p.y);
    }
    // final sim14 with qff params, 1 layer (uniform theta)
#pragma unroll 1
    for (int step = 0; step < 32; ++step) {
        float2 tq = tabq[step];
        apply_op(st, lane, c_OPC[step], c_OPT[step], tq.x, tq.y);
    }

    // dump state to shared (swizzled) for expectation values
    __syncthreads();
#pragma unroll
    for (int r = 0; r < 8; ++r) {
        int n = (lane << 5) | (r << 2) | warp;
        sbuf[OIDX(n)] = st[r];
    }
    __syncthreads();

#pragma unroll 1
    for (int w = 0; w < 7; ++w) {
        const float* Aw = A_obs + w * 6;
        const float* Bw = B_obs + w * 6;
        const float* Dw = D_obs + w * 4;
        float d0 = 2.f * Dw[1], d1 = 2.f * Dw[2], d2 = 2.f * Dw[3];
        float a10 = Aw[0], b10 = Bw[0], a20 = Aw[1], b20 = Bw[1], a21 = Aw[2], b21 = Bw[2];
        float a30 = Aw[3], b30 = Bw[3], a31 = Aw[4], b31 = Bw[4], a32 = Aw[5], b32 = Bw[5];
        int b1 = 8 - w;
        int m1 = 1 << b1, m0 = m1 << 1;
        int lowmask = m1 - 1;
        float acc = 0.f;
#pragma unroll
        for (int it = 0; it < 2; ++it) {
            int gi = tid + it * 128;
            int n = ((gi & ~lowmask) << 2) | (gi & lowmask);
            float2 v0 = sbuf[OIDX(n)];
            float2 v1 = sbuf[OIDX(n + m1)];
            float2 v2 = sbuf[OIDX(n + m0)];
            float2 v3 = sbuf[OIDX(n + m0 + m1)];
            acc += d0 * (v0.x * v0.x + v0.y * v0.y);
            acc += d1 * (v1.x * v1.x + v1.y * v1.y);
            acc += d2 * (v2.x * v2.x + v2.y * v2.y);
#define CROSS(vi, vj, aa, bb) { \
            float pr = vi.x * vj.x + vi.y * vj.y; \
            float pim = vi.x * vj.y - vi.y * vj.x; \
            acc += 2.f * (pr * (aa) - pim * (bb)); }
            CROSS(v1, v0, a10, b10)
            CROSS(v2, v0, a20, b20)
            CROSS(v2, v1, a21, b21)
            CROSS(v3, v0, a30, b30)
            CROSS(v3, v1, a31, b31)
            CROSS(v3, v2, a32, b32)
#undef CROSS
        }
#pragma unroll
        for (int off = 16; off; off >>= 1) acc += __shfl_xor_sync(FULLMASK, acc, off);
        if (lane == 0) part[w * 4 + warp] = acc;
    }
    __syncthreads();

    // head: out[b][j] = sum_w e[w] * head_w[j*7+w] + head_b[j]
    {
        int j = tid;
        float o = head_b[j];
#pragma unroll
        for (int w = 0; w < 7; ++w) {
            float e = part[w*4] + part[w*4+1] + part[w*4+2] + part[w*4+3];
            o = fmaf(e, head_w[j * 7 + w], o);
        }
        out[b * 128 + j] = o;
    }
}

// ---------------- fused MLP kernel: 2 batch rows per block (round-2 exact) ----------------
__global__ void __launch_bounds__(256) k_mlp(
    const float* __restrict__ t, const float* __restrict__ z_t,
    const float* __restrict__ te_w1, const float* __restrict__ te_b1,
    const float* __restrict__ te_w2, const float* __restrict__ te_b2,
    const float* __restrict__ ip_w1, const float* __restrict__ ip_b1,
    const float* __restrict__ ip_w2, const float* __restrict__ ip_b2) {
    __shared__ float emb[2][128];
    __shared__ float hb[2][128];
    __shared__ float cat[2][256];
    __shared__ float g1[2][256];
    const int tid = threadIdx.x;
    const int r0 = blockIdx.x * 2;

    // stage A: sinusoidal embedding + copy z_t into cat
    {
        int row = tid >> 7, i = tid & 127;
        float tv = t[r0 + row];
        int ii = i & 63;
        float f = expf(-0.14391156831212787f * (float)ii);
        float a = tv * f;
        emb[row][i] = (i < 64) ? cosf(a) : sinf(a);
        cat[row][i] = z_t[(r0 + row) * 128 + i];
    }
    __syncthreads();

    // stage B: h = silu(te_w1 @ emb + te_b1)
    if (tid < 128) {
        int j = tid;
        float a0 = te_b1[j], a1 = a0;
        const float4* w4 = reinterpret_cast<const float4*>(te_w1 + j * 128);
#pragma unroll 8
        for (int k4 = 0; k4 < 32; ++k4) {
            float4 wv = w4[k4];
            float4 x0 = *reinterpret_cast<const float4*>(&emb[0][k4 * 4]);
            float4 x1 = *reinterpret_cast<const float4*>(&emb[1][k4 * 4]);
            a0 = fmaf(wv.x, x0.x, a0); a0 = fmaf(wv.y, x0.y, a0);
            a0 = fmaf(wv.z, x0.z, a0); a0 = fmaf(wv.w, x0.w, a0);
            a1 = fmaf(wv.x, x1.x, a1); a1 = fmaf(wv.y, x1.y, a1);
            a1 = fmaf(wv.z, x1.z, a1); a1 = fmaf(wv.w, x1.w, a1);
        }
        hb[0][j] = silu_f(a0); hb[1][j] = silu_f(a1);
    }
    __syncthreads();

    // stage C: t_emb2 = te_w2 @ h + te_b2 -> cat[., 128+j]
    if (tid < 128) {
        int j = tid;
        float a0 = te_b2[j], a1 = a0;
        const float4* w4 = reinterpret_cast<const float4*>(te_w2 + j * 128);
#pragma unroll 8
        for (int k4 = 0; k4 < 32; ++k4) {
            float4 wv = w4[k4];
            float4 x0 = *reinterpret_cast<const float4*>(&hb[0][k4 * 4]);
            float4 x1 = *reinterpret_cast<const float4*>(&hb[1][k4 * 4]);
            a0 = fmaf(wv.x, x0.x, a0); a0 = fmaf(wv.y, x0.y, a0);
            a0 = fmaf(wv.z, x0.z, a0); a0 = fmaf(wv.w, x0.w, a0);
            a1 = fmaf(wv.x, x1.x, a1); a1 = fmaf(wv.y, x1.y, a1);
            a1 = fmaf(wv.z, x1.z, a1); a1 = fmaf(wv.w, x1.w, a1);
        }
        cat[0][128 + j] = a0; cat[1][128 + j] = a1;
    }
    __syncthreads();

    // stage D: g1 = silu(ip_w1 @ cat + ip_b1)
    {
        int j = tid;
        float a0 = ip_b1[j], a1 = a0;
        const float4* w4 = reinterpret_cast<const float4*>(ip_w1 + j * 256);
#pragma unroll 8
        for (int k4 = 0; k4 < 64; ++k4) {
            float4 wv = w4[k4];
            float4 x0 = *reinterpret_cast<const float4*>(&cat[0][k4 * 4]);
            float4 x1 = *reinterpret_cast<const float4*>(&cat[1][k4 * 4]);
            a0 = fmaf(wv.x, x0.x, a0); a0 = fmaf(wv.y, x0.y, a0);
            a0 = fmaf(wv.z, x0.z, a0); a0 = fmaf(wv.w, x0.w, a0);
            a1 = fmaf(wv.x, x1.x, a1); a1 = fmaf(wv.y, x1.y, a1);
            a1 = fmaf(wv.z, x1.z, a1); a1 = fmaf(wv.w, x1.w, a1);
        }
        g1[0][j] = silu_f(a0); g1[1][j] = silu_f(a1);
    }
    __syncthreads();

    // stage E: ts = sigmoid(ip_w2 @ g1 + ip_b2) * 2pi
    {
        int j = tid;
        float a0 = ip_b2[j], a1 = a0;
        const float4* w4 = reinterpret_cast<const float4*>(ip_w2 + j * 256);
#pragma unroll 8
        for (int k4 = 0; k4 < 64; ++k4) {
            float4 wv = w4[k4];
            float4 x0 = *reinterpret_cast<const float4*>(&g1[0][k4 * 4]);
            float4 x1 = *reinterpret_cast<const float4*>(&g1[1][k4 * 4]);
            a0 = fmaf(wv.x, x0.x, a0); a0 = fmaf(wv.y, x0.y, a0);
            a0 = fmaf(wv.z, x0.z, a0); a0 = fmaf(wv.w, x0.w, a0);
            a1 = fmaf(wv.x, x1.x, a1); a1 = fmaf(wv.y, x1.y, a1);
            a1 = fmaf(wv.z, x1.z, a1); a1 = fmaf(wv.w, x1.w, a1);
        }
        g_ts[r0 * 256 + j]       = TWO_PI_F / (1.f + expf(-a0));
        g_ts[(r0 + 1) * 256 + j] = TWO_PI_F / (1.f + expf(-a1));
    }
}

// ---------------- launch ----------------
extern "C" void kernel_launch(void* const* d_in, const int* in_sizes, int n_in,
                              void* d_out, int out_size) {
    const float* z_t    = (const float*)d_in[0];
    const float* t      = (const float*)d_in[1];
    const float* te_w1  = (const float*)d_in[2];
    const float* te_b1  = (const float*)d_in[3];
    const float* te_w2  = (const float*)d_in[4];
    const float* te_b2  = (const float*)d_in[5];
    const float* ip_w1  = (const float*)d_in[6];
    const float* ip_b1  = (const float*)d_in[7];
    const float* ip_w2  = (const float*)d_in[8];
    const float* ip_b2  = (const float*)d_in[9];
    const float* prep   = (const float*)d_in[10];
    const float* sig    = (const float*)d_in[11];
    const float* qff    = (const float*)d_in[12];
    const float* A_obs  = (const float*)d_in[13];
    const float* B_obs  = (const float*)d_in[14];
    const float* D_obs  = (const float*)d_in[15];
    const float* head_w = (const float*)d_in[16];
    const float* head_b = (const float*)d_in[17];
    float* out = (float*)d_out;

    k_mlp<<<128, 256>>>(t, z_t, te_w1, te_b1, te_w2, te_b2, ip_w1, ip_b1, ip_w2, ip_b2);
    k_sim<<<256, 128>>>(prep, sig, qff, A_obs, B_obs, D_obs, head_w, head_b, out);
}